// round 13
// baseline (speedup 1.0000x reference)
#include <cuda_runtime.h>
#include <cstdint>
#include <math.h>

#define N_TOK 16384
#define DDIM  2048
#define NEXP  64
#define TOPK  8
#define BM    128
#define KC    32
#define NC    (DDIM/KC)
#define THREADS 256

#define A_STRIDE 36
#define B_STRIDE 72
#define A_WORDS  (4*128*A_STRIDE)          // 18432
#define B_WORDS  (4*KC*B_STRIDE)           // 9216
#define SM_WORDS (A_WORDS + B_WORDS)       // 27648
#define SM_BYTES (SM_WORDS*4)              // 110592

// post-GEMM smem carve (word offsets into smw)
#define SS_OFF    0                         // Ss[128][65] = 8320 words
#define FLAGC_OFF 8320
#define FLAGL_OFF 8322                      // 128 ints
#define EXACT_OFF 8452                      // 64 floats

static __device__ __forceinline__ uint32_t tf32r(float v) {
    uint32_t u; asm("cvt.rna.tf32.f32 %0, %1;" : "=r"(u) : "f"(v));
    return u;
}

#define MMA_TF32(d, a, b) \
    asm("mma.sync.aligned.m16n8k8.row.col.f32.tf32.tf32.f32 " \
        "{%0,%1,%2,%3}, {%4,%5,%6,%7}, {%8,%9}, {%0,%1,%2,%3};" \
        : "+f"((d)[0]), "+f"((d)[1]), "+f"((d)[2]), "+f"((d)[3]) \
        : "r"((a)[0]), "r"((a)[1]), "r"((a)[2]), "r"((a)[3]), \
          "r"((b)[0]), "r"((b)[1]))

__global__ __launch_bounds__(THREADS, 1)
void noisyk_gate_mma(const float* __restrict__ x,
                     const float* __restrict__ W,
                     const float* __restrict__ bias,
                     float* __restrict__ g_out,
                     float* __restrict__ idx_out,
                     float* __restrict__ sc_out)
{
    extern __shared__ __align__(16) uint32_t smw[];
    float* Ss = (float*)(smw + SS_OFF);

    const int tid = threadIdx.x;
    const int w   = tid >> 5;
    const int l   = tid & 31;
    const int g   = l >> 2;
    const int t   = l & 3;
    const int tokW = 32 * (w & 3);
    const int nW   = 32 * (w >> 2);
    const int tokRow = blockIdx.x * BM;

    const int a_tok = tid >> 1;
    const int a_kq  = (tid & 1) * 16;
    const float* a_src = x + (size_t)(tokRow + a_tok) * DDIM + a_kq;
    const int b_k  = tid >> 3;
    const int b_ne = (tid & 7) * 8;
    const float* b_src = W + (size_t)b_k * NEXP + b_ne;

    // ---- stage chunk 0 (hi/lo 2-way tf32 split) ----
    {
        #pragma unroll
        for (int j = 0; j < 4; j++) {
            float4 v = *(const float4*)(a_src + 4 * j);
            float vv[4] = {v.x, v.y, v.z, v.w};
            uint32_t hi[4], lo[4];
            #pragma unroll
            for (int q = 0; q < 4; q++) {
                hi[q] = tf32r(vv[q]);
                lo[q] = tf32r(vv[q] - __uint_as_float(hi[q]));
            }
            const int off = a_tok * A_STRIDE + a_kq + 4 * j;
            *(uint4*)&smw[(0 * 128) * A_STRIDE + off] = make_uint4(hi[0], hi[1], hi[2], hi[3]);
            *(uint4*)&smw[(1 * 128) * A_STRIDE + off] = make_uint4(lo[0], lo[1], lo[2], lo[3]);
        }
        #pragma unroll
        for (int j = 0; j < 2; j++) {
            float4 v = *(const float4*)(b_src + 4 * j);
            float vv[4] = {v.x, v.y, v.z, v.w};
            uint32_t hi[4], lo[4];
            #pragma unroll
            for (int q = 0; q < 4; q++) {
                hi[q] = tf32r(vv[q]);
                lo[q] = tf32r(vv[q] - __uint_as_float(hi[q]));
            }
            const int off = b_k * B_STRIDE + b_ne + 4 * j;
            *(uint4*)&smw[A_WORDS + (0 * KC) * B_STRIDE + off] = make_uint4(hi[0], hi[1], hi[2], hi[3]);
            *(uint4*)&smw[A_WORDS + (1 * KC) * B_STRIDE + off] = make_uint4(lo[0], lo[1], lo[2], lo[3]);
        }
    }

    float acc_s[2][4][4], acc_g[2][4][4], acc_sm[2][4][4];
    #pragma unroll
    for (int mi = 0; mi < 2; mi++)
        #pragma unroll
        for (int ni = 0; ni < 4; ni++)
            #pragma unroll
            for (int q = 0; q < 4; q++) {
                acc_s[mi][ni][q] = 0.0f; acc_g[mi][ni][q] = 0.0f; acc_sm[mi][ni][q] = 0.0f;
            }

    __syncthreads();

    int buf = 0;
    for (int kt = 0; kt < NC; ++kt) {
        float4 pa[4], pb[2];
        if (kt + 1 < NC) {
            const int kb = (kt + 1) * KC;
            #pragma unroll
            for (int j = 0; j < 4; j++) pa[j] = *(const float4*)(a_src + kb + 4 * j);
            #pragma unroll
            for (int j = 0; j < 2; j++) pb[j] = *(const float4*)(b_src + (size_t)kb * NEXP + 4 * j);
        }

        const uint32_t* Ah = &smw[((buf * 2 + 0) * 128) * A_STRIDE];
        const uint32_t* Al = &smw[((buf * 2 + 1) * 128) * A_STRIDE];
        const uint32_t* Bh = &smw[A_WORDS + ((buf * 2 + 0) * KC) * B_STRIDE];
        const uint32_t* Bl = &smw[A_WORDS + ((buf * 2 + 1) * KC) * B_STRIDE];

        #pragma unroll
        for (int s = 0; s < 4; ++s) {
            const int k0 = s * 8;
            uint32_t a_h[2][4], a_l[2][4], b_h[4][2], b_l[4][2];
            #pragma unroll
            for (int mi = 0; mi < 2; mi++) {
                #pragma unroll
                for (int c = 0; c < 4; c++) {
                    const int row = tokW + mi * 16 + g + ((c & 1) << 3);
                    const int col = k0 + t + ((c >> 1) << 2);
                    a_h[mi][c] = Ah[row * A_STRIDE + col];
                    a_l[mi][c] = Al[row * A_STRIDE + col];
                }
            }
            #pragma unroll
            for (int ni = 0; ni < 4; ni++) {
                #pragma unroll
                for (int c = 0; c < 2; c++) {
                    const int row = k0 + t + (c << 2);
                    const int col = nW + ni * 8 + g;
                    b_h[ni][c] = Bh[row * B_STRIDE + col];
                    b_l[ni][c] = Bl[row * B_STRIDE + col];
                }
            }
            #pragma unroll
            for (int mi = 0; mi < 2; mi++) {
                #pragma unroll
                for (int ni = 0; ni < 4; ni++) {
                    MMA_TF32(acc_s[mi][ni],  a_h[mi], b_h[ni]);
                    MMA_TF32(acc_sm[mi][ni], a_h[mi], b_l[ni]);
                    MMA_TF32(acc_sm[mi][ni], a_l[mi], b_h[ni]);
                }
            }
        }

        if ((kt & 7) == 7) {
            #pragma unroll
            for (int mi = 0; mi < 2; mi++)
                #pragma unroll
                for (int ni = 0; ni < 4; ni++)
                    #pragma unroll
                    for (int q = 0; q < 4; q++) {
                        acc_g[mi][ni][q] += acc_s[mi][ni][q];
                        acc_s[mi][ni][q] = 0.0f;
                    }
        }

        if (kt + 1 < NC) {
            const int nb = buf ^ 1;
            #pragma unroll
            for (int j = 0; j < 4; j++) {
                float vv[4] = {pa[j].x, pa[j].y, pa[j].z, pa[j].w};
                uint32_t hi[4], lo[4];
                #pragma unroll
                for (int q = 0; q < 4; q++) {
                    hi[q] = tf32r(vv[q]);
                    lo[q] = tf32r(vv[q] - __uint_as_float(hi[q]));
                }
                const int off = a_tok * A_STRIDE + a_kq + 4 * j;
                *(uint4*)&smw[((nb * 2 + 0) * 128) * A_STRIDE + off] = make_uint4(hi[0], hi[1], hi[2], hi[3]);
                *(uint4*)&smw[((nb * 2 + 1) * 128) * A_STRIDE + off] = make_uint4(lo[0], lo[1], lo[2], lo[3]);
            }
            #pragma unroll
            for (int j = 0; j < 2; j++) {
                float vv[4] = {pb[j].x, pb[j].y, pb[j].z, pb[j].w};
                uint32_t hi[4], lo[4];
                #pragma unroll
                for (int q = 0; q < 4; q++) {
                    hi[q] = tf32r(vv[q]);
                    lo[q] = tf32r(vv[q] - __uint_as_float(hi[q]));
                }
                const int off = b_k * B_STRIDE + b_ne + 4 * j;
                *(uint4*)&smw[A_WORDS + ((nb * 2 + 0) * KC) * B_STRIDE + off] = make_uint4(hi[0], hi[1], hi[2], hi[3]);
                *(uint4*)&smw[A_WORDS + ((nb * 2 + 1) * KC) * B_STRIDE + off] = make_uint4(lo[0], lo[1], lo[2], lo[3]);
            }
        }
        __syncthreads();
        buf ^= 1;
    }

    // ---- epilogue: bias + sigmoid, scores ----
    #pragma unroll
    for (int mi = 0; mi < 2; mi++) {
        #pragma unroll
        for (int ni = 0; ni < 4; ni++) {
            const int r0 = tokW + mi * 16 + g;
            const int r1 = r0 + 8;
            const int c0 = nW + ni * 8 + 2 * t;
            const float b0 = bias[c0], b1 = bias[c0 + 1];
            float z[4] = {(acc_g[mi][ni][0] + acc_sm[mi][ni][0]) + b0,
                          (acc_g[mi][ni][1] + acc_sm[mi][ni][1]) + b1,
                          (acc_g[mi][ni][2] + acc_sm[mi][ni][2]) + b0,
                          (acc_g[mi][ni][3] + acc_sm[mi][ni][3]) + b1};
            float s[4];
            #pragma unroll
            for (int q = 0; q < 4; q++) {
                if (z[q] >= 0.0f) s[q] = 1.0f / (1.0f + expf(-z[q]));
                else { float e = expf(z[q]); s[q] = e / (1.0f + e); }
            }
            Ss[r0 * 65 + c0]     = s[0];
            Ss[r0 * 65 + c0 + 1] = s[1];
            Ss[r1 * 65 + c0]     = s[2];
            Ss[r1 * 65 + c0 + 1] = s[3];
            *(float2*)(sc_out + (size_t)(tokRow + r0) * NEXP + c0) = make_float2(s[0], s[1]);
            *(float2*)(sc_out + (size_t)(tokRow + r1) * NEXP + c0) = make_float2(s[2], s[3]);
        }
    }

    int* flagcnt  = (int*)(smw + FLAGC_OFF);
    int* flaglist = (int*)(smw + FLAGL_OFF);
    if (tid == 0) *flagcnt = 0;
    __syncthreads();

    // ---- top-9 per token; flag knife-edge tokens ----
    if (tid < BM) {
        float vals[9];
        int   ids[9];
        #pragma unroll
        for (int j = 0; j < 9; j++) { vals[j] = -1e30f; ids[j] = 0; }
        for (int e = 0; e < NEXP; e++) {
            float sv = Ss[tid * 65 + e];
            if (sv > vals[8]) {
                int p = 8;
                while (p > 0 && sv > vals[p - 1]) {
                    vals[p] = vals[p - 1]; ids[p] = ids[p - 1]; p--;
                }
                vals[p] = sv; ids[p] = e;
            }
        }
        bool knife = false;
        #pragma unroll
        for (int j = 0; j < 8; j++)
            if (vals[j] - vals[j + 1] < 1e-5f) knife = true;

        if (!knife) {
            float sum = 0.0f;
            #pragma unroll
            for (int j = 0; j < TOPK; j++) sum += vals[j];
            const float inv = 1.0f / sum;
            const size_t base = (size_t)(tokRow + tid) * TOPK;
            #pragma unroll
            for (int j = 0; j < TOPK; j++) {
                g_out[base + j]   = vals[j] * inv;
                idx_out[base + j] = (float)ids[j];
            }
        } else {
            int pos = atomicAdd(flagcnt, 1);
            flaglist[pos] = tid;
        }
    }
    __syncthreads();

    // ---- flagged tokens: bit-exact replay of the R5 hierarchical fp32 order
    //      (tile of 16 fma-chain -> 16-tile super -> 8-super grand), which is
    //      empirically reference-matching at knife-edge tokens ----
    const int nflag = *flagcnt;
    float* exactf = (float*)(smw + EXACT_OFF);    // [64]
    for (int i = 0; i < nflag; i++) {
        const int tok = flaglist[i];
        if (tid < NEXP) {
            const float* xr = x + (size_t)(tokRow + tok) * DDIM;
            const float* wp = W + tid;
            float grand = 0.0f;
            for (int sc = 0; sc < 8; sc++) {
                float sup = 0.0f;
                for (int t2 = 0; t2 < 16; t2++) {
                    const int k0 = sc * 256 + t2 * 16;
                    float tile = __fmul_rn(xr[k0], wp[(size_t)k0 * NEXP]);
                    #pragma unroll
                    for (int kk = 1; kk < 16; kk++)
                        tile = __fmaf_rn(xr[k0 + kk], wp[(size_t)(k0 + kk) * NEXP], tile);
                    sup = (t2 == 0) ? tile : __fadd_rn(sup, tile);
                }
                grand = (sc == 0) ? sup : __fadd_rn(grand, sup);
            }
            float z = grand + bias[tid];
            float s;
            if (z >= 0.0f) {
                s = 1.0f / (1.0f + expf(-z));
            } else {
                float e = expf(z);
                s = e / (1.0f + e);
            }
            exactf[tid] = s;
        }
        __syncthreads();
        if (tid == 0) {
            float vals[TOPK];
            int   ids[TOPK];
            #pragma unroll
            for (int j = 0; j < TOPK; j++) { vals[j] = -1e30f; ids[j] = 0; }
            for (int e2 = 0; e2 < NEXP; e2++) {
                float sv = exactf[e2];
                if (sv > vals[TOPK - 1]) {
                    int p = TOPK - 1;
                    while (p > 0 && sv > vals[p - 1]) {
                        vals[p] = vals[p - 1]; ids[p] = ids[p - 1]; p--;
                    }
                    vals[p] = sv; ids[p] = e2;
                }
            }
            float sum = 0.0f;
            #pragma unroll
            for (int j = 0; j < TOPK; j++) sum += vals[j];
            const float inv = 1.0f / sum;
            const size_t base = (size_t)(tokRow + tok) * TOPK;
            #pragma unroll
            for (int j = 0; j < TOPK; j++) {
                g_out[base + j]   = vals[j] * inv;
                idx_out[base + j] = (float)ids[j];
            }
        }
        __syncthreads();
    }
}

extern "C" void kernel_launch(void* const* d_in, const int* in_sizes, int n_in,
                              void* d_out, int out_size)
{
    const float* x = (const float*)d_in[0];
    const float* W = (const float*)d_in[1];
    const float* b = (const float*)d_in[2];

    float* out     = (float*)d_out;
    float* g_out   = out;
    float* idx_out = out + (size_t)N_TOK * TOPK;
    float* sc_out  = out + (size_t)2 * N_TOK * TOPK;

    cudaFuncSetAttribute(noisyk_gate_mma,
                         cudaFuncAttributeMaxDynamicSharedMemorySize, SM_BYTES);
    noisyk_gate_mma<<<N_TOK / BM, THREADS, SM_BYTES>>>(x, W, b, g_out, idx_out, sc_out);
}

// round 14
// speedup vs baseline: 1.7382x; 1.7382x over previous
#include <cuda_runtime.h>
#include <cstdint>
#include <math.h>

#define N_TOK 16384
#define DDIM  2048
#define NEXP  64
#define TOPK  8
#define BM    128
#define KC    32
#define NC    (DDIM/KC)
#define THREADS 512

#define A_STRIDE 36
#define B_STRIDE 72
#define A_WORDS  (4*128*A_STRIDE)          // [buf][ver][128][36] = 18432*... total words
#define B_WORDS  (4*KC*B_STRIDE)           // [buf][ver][32][72]
#define SM_WORDS (A_WORDS + B_WORDS)       // 27648
#define SM_BYTES (SM_WORDS*4)              // 110592

// post-GEMM smem carve (word offsets)
#define SS_OFF    0                         // Ss[128][65] = 8320 words
#define FLAGC_OFF 8320
#define FLAGL_OFF 8322                      // 128 ints
#define PART_OFF  8452                      // 512 floats [64 exp][8 sc]
#define EXACT_OFF 8964                      // 64 floats

static __device__ __forceinline__ uint32_t tf32r(float v) {
    uint32_t u; asm("cvt.rna.tf32.f32 %0, %1;" : "=r"(u) : "f"(v));
    return u;
}

#define MMA_TF32(d, a, b) \
    asm("mma.sync.aligned.m16n8k8.row.col.f32.tf32.tf32.f32 " \
        "{%0,%1,%2,%3}, {%4,%5,%6,%7}, {%8,%9}, {%0,%1,%2,%3};" \
        : "+f"((d)[0]), "+f"((d)[1]), "+f"((d)[2]), "+f"((d)[3]) \
        : "r"((a)[0]), "r"((a)[1]), "r"((a)[2]), "r"((a)[3]), \
          "r"((b)[0]), "r"((b)[1]))

__global__ __launch_bounds__(THREADS, 1)
void noisyk_gate_mma(const float* __restrict__ x,
                     const float* __restrict__ W,
                     const float* __restrict__ bias,
                     float* __restrict__ g_out,
                     float* __restrict__ idx_out,
                     float* __restrict__ sc_out)
{
    extern __shared__ __align__(16) uint32_t smw[];
    float* Ss = (float*)(smw + SS_OFF);

    const int tid = threadIdx.x;
    const int w   = tid >> 5;
    const int l   = tid & 31;
    const int g   = l >> 2;                 // 0..7
    const int t   = l & 3;                  // 0..3
    const int tokW = 16 * (w & 7);          // warp token base (16 rows)
    const int nW   = 32 * (w >> 3);         // warp expert base (32 cols)
    const int tokRow = blockIdx.x * BM;

    // ---- staging maps (512 threads, KC=32) ----
    // A: 128 tok x 32 k = 1024 float4; chunk c = tid + 512*j
    // B: 32 k x 64 exp = 512 float4; c = tid
    const int b_k  = tid >> 4;              // 0..31
    const int b_ne = (tid & 15) * 4;        // 0..60
    const float* b_src = W + (size_t)b_k * NEXP + b_ne;

    // ---- stage chunk 0 (hi/lo 2-way tf32 split) ----
    {
        #pragma unroll
        for (int j = 0; j < 2; j++) {
            const int c = tid + 512 * j;
            const int tok = c >> 3, koff = (c & 7) * 4;
            float4 v = *(const float4*)(x + (size_t)(tokRow + tok) * DDIM + koff);
            float vv[4] = {v.x, v.y, v.z, v.w};
            uint32_t hi[4], lo[4];
            #pragma unroll
            for (int q = 0; q < 4; q++) {
                hi[q] = tf32r(vv[q]);
                lo[q] = tf32r(vv[q] - __uint_as_float(hi[q]));
            }
            const int off = tok * A_STRIDE + koff;
            *(uint4*)&smw[(0 * 128) * A_STRIDE + off] = make_uint4(hi[0], hi[1], hi[2], hi[3]);
            *(uint4*)&smw[(1 * 128) * A_STRIDE + off] = make_uint4(lo[0], lo[1], lo[2], lo[3]);
        }
        {
            float4 v = *(const float4*)(b_src);
            float vv[4] = {v.x, v.y, v.z, v.w};
            uint32_t hi[4], lo[4];
            #pragma unroll
            for (int q = 0; q < 4; q++) {
                hi[q] = tf32r(vv[q]);
                lo[q] = tf32r(vv[q] - __uint_as_float(hi[q]));
            }
            const int off = b_k * B_STRIDE + b_ne;
            *(uint4*)&smw[A_WORDS + (0 * KC) * B_STRIDE + off] = make_uint4(hi[0], hi[1], hi[2], hi[3]);
            *(uint4*)&smw[A_WORDS + (1 * KC) * B_STRIDE + off] = make_uint4(lo[0], lo[1], lo[2], lo[3]);
        }
    }

    float acc_hh[4][4], acc_sm[4][4];
    #pragma unroll
    for (int ni = 0; ni < 4; ni++)
        #pragma unroll
        for (int q = 0; q < 4; q++) { acc_hh[ni][q] = 0.0f; acc_sm[ni][q] = 0.0f; }

    __syncthreads();

    int buf = 0;
    for (int kt = 0; kt < NC; ++kt) {
        float4 pa[2], pb;
        if (kt + 1 < NC) {
            const int kb = (kt + 1) * KC;
            #pragma unroll
            for (int j = 0; j < 2; j++) {
                const int c = tid + 512 * j;
                const int tok = c >> 3, koff = (c & 7) * 4;
                pa[j] = *(const float4*)(x + (size_t)(tokRow + tok) * DDIM + kb + koff);
            }
            pb = *(const float4*)(b_src + (size_t)kb * NEXP);
        }

        const uint32_t* Ah = &smw[((buf * 2 + 0) * 128) * A_STRIDE];
        const uint32_t* Al = &smw[((buf * 2 + 1) * 128) * A_STRIDE];
        const uint32_t* Bh = &smw[A_WORDS + ((buf * 2 + 0) * KC) * B_STRIDE];
        const uint32_t* Bl = &smw[A_WORDS + ((buf * 2 + 1) * KC) * B_STRIDE];

        #pragma unroll
        for (int s = 0; s < 4; ++s) {
            const int k0 = s * 8;
            uint32_t a_h[4], a_l[4], b_h[4][2], b_l[4][2];
            #pragma unroll
            for (int c = 0; c < 4; c++) {
                const int row = tokW + g + ((c & 1) << 3);
                const int col = k0 + t + ((c >> 1) << 2);
                a_h[c] = Ah[row * A_STRIDE + col];
                a_l[c] = Al[row * A_STRIDE + col];
            }
            #pragma unroll
            for (int ni = 0; ni < 4; ni++) {
                #pragma unroll
                for (int c = 0; c < 2; c++) {
                    const int row = k0 + t + (c << 2);
                    const int col = nW + ni * 8 + g;
                    b_h[ni][c] = Bh[row * B_STRIDE + col];
                    b_l[ni][c] = Bl[row * B_STRIDE + col];
                }
            }
            #pragma unroll
            for (int ni = 0; ni < 4; ni++) {
                MMA_TF32(acc_hh[ni], a_h, b_h[ni]);
                MMA_TF32(acc_sm[ni], a_h, b_l[ni]);
                MMA_TF32(acc_sm[ni], a_l, b_h[ni]);
            }
        }

        if (kt + 1 < NC) {
            const int nb = buf ^ 1;
            #pragma unroll
            for (int j = 0; j < 2; j++) {
                const int c = tid + 512 * j;
                const int tok = c >> 3, koff = (c & 7) * 4;
                float vv[4] = {pa[j].x, pa[j].y, pa[j].z, pa[j].w};
                uint32_t hi[4], lo[4];
                #pragma unroll
                for (int q = 0; q < 4; q++) {
                    hi[q] = tf32r(vv[q]);
                    lo[q] = tf32r(vv[q] - __uint_as_float(hi[q]));
                }
                const int off = tok * A_STRIDE + koff;
                *(uint4*)&smw[((nb * 2 + 0) * 128) * A_STRIDE + off] = make_uint4(hi[0], hi[1], hi[2], hi[3]);
                *(uint4*)&smw[((nb * 2 + 1) * 128) * A_STRIDE + off] = make_uint4(lo[0], lo[1], lo[2], lo[3]);
            }
            {
                float vv[4] = {pb.x, pb.y, pb.z, pb.w};
                uint32_t hi[4], lo[4];
                #pragma unroll
                for (int q = 0; q < 4; q++) {
                    hi[q] = tf32r(vv[q]);
                    lo[q] = tf32r(vv[q] - __uint_as_float(hi[q]));
                }
                const int off = b_k * B_STRIDE + b_ne;
                *(uint4*)&smw[A_WORDS + ((nb * 2 + 0) * KC) * B_STRIDE + off] = make_uint4(hi[0], hi[1], hi[2], hi[3]);
                *(uint4*)&smw[A_WORDS + ((nb * 2 + 1) * KC) * B_STRIDE + off] = make_uint4(lo[0], lo[1], lo[2], lo[3]);
            }
        }
        __syncthreads();
        buf ^= 1;
    }

    // ---- epilogue: bias + sigmoid, scores ----
    #pragma unroll
    for (int ni = 0; ni < 4; ni++) {
        const int r0 = tokW + g;
        const int r1 = r0 + 8;
        const int c0 = nW + ni * 8 + 2 * t;
        const float b0 = bias[c0], b1 = bias[c0 + 1];
        float z[4] = {(acc_hh[ni][0] + acc_sm[ni][0]) + b0,
                      (acc_hh[ni][1] + acc_sm[ni][1]) + b1,
                      (acc_hh[ni][2] + acc_sm[ni][2]) + b0,
                      (acc_hh[ni][3] + acc_sm[ni][3]) + b1};
        float s[4];
        #pragma unroll
        for (int q = 0; q < 4; q++) {
            if (z[q] >= 0.0f) s[q] = 1.0f / (1.0f + expf(-z[q]));
            else { float e = expf(z[q]); s[q] = e / (1.0f + e); }
        }
        Ss[r0 * 65 + c0]     = s[0];
        Ss[r0 * 65 + c0 + 1] = s[1];
        Ss[r1 * 65 + c0]     = s[2];
        Ss[r1 * 65 + c0 + 1] = s[3];
        *(float2*)(sc_out + (size_t)(tokRow + r0) * NEXP + c0) = make_float2(s[0], s[1]);
        *(float2*)(sc_out + (size_t)(tokRow + r1) * NEXP + c0) = make_float2(s[2], s[3]);
    }

    int* flagcnt  = (int*)(smw + FLAGC_OFF);
    int* flaglist = (int*)(smw + FLAGL_OFF);
    if (tid == 0) *flagcnt = 0;
    __syncthreads();

    // ---- top-9 per token; flag knife-edge tokens ----
    if (tid < BM) {
        float vals[9];
        int   ids[9];
        #pragma unroll
        for (int j = 0; j < 9; j++) { vals[j] = -1e30f; ids[j] = 0; }
        for (int e = 0; e < NEXP; e++) {
            float sv = Ss[tid * 65 + e];
            if (sv > vals[8]) {
                int p = 8;
                while (p > 0 && sv > vals[p - 1]) {
                    vals[p] = vals[p - 1]; ids[p] = ids[p - 1]; p--;
                }
                vals[p] = sv; ids[p] = e;
            }
        }
        bool knife = false;
        #pragma unroll
        for (int j = 0; j < 8; j++)
            if (vals[j] - vals[j + 1] < 1e-5f) knife = true;

        if (!knife) {
            float sum = 0.0f;
            #pragma unroll
            for (int j = 0; j < TOPK; j++) sum += vals[j];
            const float inv = 1.0f / sum;
            const size_t base = (size_t)(tokRow + tid) * TOPK;
            #pragma unroll
            for (int j = 0; j < TOPK; j++) {
                g_out[base + j]   = vals[j] * inv;
                idx_out[base + j] = (float)ids[j];
            }
        } else {
            int pos = atomicAdd(flagcnt, 1);
            flaglist[pos] = tid;
        }
    }
    __syncthreads();

    // ---- flagged tokens: bit-exact R5-order replay, parallel over
    //      64 experts x 8 superchunks (strict left folds preserved) ----
    const int nflag = *flagcnt;
    float* part   = (float*)(smw + PART_OFF);   // [64 exp][8 sc]
    float* exactf = (float*)(smw + EXACT_OFF);  // [64]
    for (int i = 0; i < nflag; i++) {
        const int tok = flaglist[i];
        {
            const int e  = tid & 63;
            const int sc = tid >> 6;             // 0..7
            const float* xr = x + (size_t)(tokRow + tok) * DDIM;
            const float* wp = W + e;
            float sup = 0.0f;
            for (int t2 = 0; t2 < 16; t2++) {
                const int k0 = sc * 256 + t2 * 16;
                float tile = __fmul_rn(xr[k0], wp[(size_t)k0 * NEXP]);
                #pragma unroll
                for (int kk = 1; kk < 16; kk++)
                    tile = __fmaf_rn(xr[k0 + kk], wp[(size_t)(k0 + kk) * NEXP], tile);
                sup = (t2 == 0) ? tile : __fadd_rn(sup, tile);
            }
            part[e * 8 + sc] = sup;
        }
        __syncthreads();
        if (tid < NEXP) {
            float grand = part[tid * 8 + 0];
            #pragma unroll
            for (int sc = 1; sc < 8; sc++)
                grand = __fadd_rn(grand, part[tid * 8 + sc]);
            float z = grand + bias[tid];
            float s;
            if (z >= 0.0f) {
                s = 1.0f / (1.0f + expf(-z));
            } else {
                float e2 = expf(z);
                s = e2 / (1.0f + e2);
            }
            exactf[tid] = s;
        }
        __syncthreads();
        if (tid == 0) {
            float vals[TOPK];
            int   ids[TOPK];
            #pragma unroll
            for (int j = 0; j < TOPK; j++) { vals[j] = -1e30f; ids[j] = 0; }
            for (int e2 = 0; e2 < NEXP; e2++) {
                float sv = exactf[e2];
                if (sv > vals[TOPK - 1]) {
                    int p = TOPK - 1;
                    while (p > 0 && sv > vals[p - 1]) {
                        vals[p] = vals[p - 1]; ids[p] = ids[p - 1]; p--;
                    }
                    vals[p] = sv; ids[p] = e2;
                }
            }
            float sum = 0.0f;
            #pragma unroll
            for (int j = 0; j < TOPK; j++) sum += vals[j];
            const float inv = 1.0f / sum;
            const size_t base = (size_t)(tokRow + tok) * TOPK;
            #pragma unroll
            for (int j = 0; j < TOPK; j++) {
                g_out[base + j]   = vals[j] * inv;
                idx_out[base + j] = (float)ids[j];
            }
        }
        __syncthreads();
    }
}

extern "C" void kernel_launch(void* const* d_in, const int* in_sizes, int n_in,
                              void* d_out, int out_size)
{
    const float* x = (const float*)d_in[0];
    const float* W = (const float*)d_in[1];
    const float* b = (const float*)d_in[2];

    float* out     = (float*)d_out;
    float* g_out   = out;
    float* idx_out = out + (size_t)N_TOK * TOPK;
    float* sc_out  = out + (size_t)2 * N_TOK * TOPK;

    cudaFuncSetAttribute(noisyk_gate_mma,
                         cudaFuncAttributeMaxDynamicSharedMemorySize, SM_BYTES);
    noisyk_gate_mma<<<N_TOK / BM, THREADS, SM_BYTES>>>(x, W, b, g_out, idx_out, sc_out);
}

// round 15
// speedup vs baseline: 1.9037x; 1.0952x over previous
#include <cuda_runtime.h>
#include <cstdint>
#include <math.h>

#define N_TOK 16384
#define DDIM  2048
#define NEXP  64
#define TOPK  8
#define BM    64
#define KC    32
#define NC    (DDIM/KC)
#define THREADS 256

#define A_STRIDE 36
#define B_STRIDE 72
#define A_WORDS  (4*BM*A_STRIDE)           // [buf][ver][64][36] = 9216 words
#define B_WORDS  (4*KC*B_STRIDE)           // [buf][ver][32][72] = 9216 words
#define SM_WORDS (A_WORDS + B_WORDS)       // 18432
#define SM_BYTES (SM_WORDS*4)              // 73728

// post-GEMM smem carve (word offsets)
#define SS_OFF    0                         // Ss[64][65] = 4160 words
#define FLAGC_OFF 4160
#define FLAGL_OFF 4162                      // 64 ints
#define PART_OFF  4228                      // 512 floats [64 exp][8 sc]
#define EXACT_OFF 4740                      // 64 floats

static __device__ __forceinline__ uint32_t tf32r(float v) {
    uint32_t u; asm("cvt.rna.tf32.f32 %0, %1;" : "=r"(u) : "f"(v));
    return u;
}

#define MMA_TF32(d, a, b) \
    asm("mma.sync.aligned.m16n8k8.row.col.f32.tf32.tf32.f32 " \
        "{%0,%1,%2,%3}, {%4,%5,%6,%7}, {%8,%9}, {%0,%1,%2,%3};" \
        : "+f"((d)[0]), "+f"((d)[1]), "+f"((d)[2]), "+f"((d)[3]) \
        : "r"((a)[0]), "r"((a)[1]), "r"((a)[2]), "r"((a)[3]), \
          "r"((b)[0]), "r"((b)[1]))

__global__ __launch_bounds__(THREADS, 2)
void noisyk_gate_mma(const float* __restrict__ x,
                     const float* __restrict__ W,
                     const float* __restrict__ bias,
                     float* __restrict__ g_out,
                     float* __restrict__ idx_out,
                     float* __restrict__ sc_out)
{
    extern __shared__ __align__(16) uint32_t smw[];
    float* Ss = (float*)(smw + SS_OFF);

    const int tid = threadIdx.x;
    const int w   = tid >> 5;
    const int l   = tid & 31;
    const int g   = l >> 2;                 // 0..7
    const int t   = l & 3;                  // 0..3
    const int tokW = 16 * (w & 3);          // warp token base (16 rows of 64)
    const int nW   = 32 * (w >> 2);         // warp expert base (32 of 64)
    const int tokRow = blockIdx.x * BM;

    // ---- staging: A = 64x32 floats (512 float4), B = 32x64 (512 float4);
    //      256 threads x 2 iterations each ----

    // ---- stage chunk 0 (hi/lo 2-way tf32 split) ----
    {
        #pragma unroll
        for (int j = 0; j < 2; j++) {
            const int c = tid + 256 * j;
            const int tok = c >> 3, koff = (c & 7) * 4;
            float4 v = *(const float4*)(x + (size_t)(tokRow + tok) * DDIM + koff);
            float vv[4] = {v.x, v.y, v.z, v.w};
            uint32_t hi[4], lo[4];
            #pragma unroll
            for (int q = 0; q < 4; q++) {
                hi[q] = tf32r(vv[q]);
                lo[q] = tf32r(vv[q] - __uint_as_float(hi[q]));
            }
            const int off = tok * A_STRIDE + koff;
            *(uint4*)&smw[(0 * BM) * A_STRIDE + off] = make_uint4(hi[0], hi[1], hi[2], hi[3]);
            *(uint4*)&smw[(1 * BM) * A_STRIDE + off] = make_uint4(lo[0], lo[1], lo[2], lo[3]);
        }
        #pragma unroll
        for (int j = 0; j < 2; j++) {
            const int c = tid + 256 * j;
            const int bk = c >> 4, bne = (c & 15) * 4;
            float4 v = *(const float4*)(W + (size_t)bk * NEXP + bne);
            float vv[4] = {v.x, v.y, v.z, v.w};
            uint32_t hi[4], lo[4];
            #pragma unroll
            for (int q = 0; q < 4; q++) {
                hi[q] = tf32r(vv[q]);
                lo[q] = tf32r(vv[q] - __uint_as_float(hi[q]));
            }
            const int off = bk * B_STRIDE + bne;
            *(uint4*)&smw[A_WORDS + (0 * KC) * B_STRIDE + off] = make_uint4(hi[0], hi[1], hi[2], hi[3]);
            *(uint4*)&smw[A_WORDS + (1 * KC) * B_STRIDE + off] = make_uint4(lo[0], lo[1], lo[2], lo[3]);
        }
    }

    float acc_hh[4][4], acc_sm[4][4];
    #pragma unroll
    for (int ni = 0; ni < 4; ni++)
        #pragma unroll
        for (int q = 0; q < 4; q++) { acc_hh[ni][q] = 0.0f; acc_sm[ni][q] = 0.0f; }

    __syncthreads();

    int buf = 0;
    for (int kt = 0; kt < NC; ++kt) {
        float4 pa[2], pb[2];
        if (kt + 1 < NC) {
            const int kb = (kt + 1) * KC;
            #pragma unroll
            for (int j = 0; j < 2; j++) {
                const int c = tid + 256 * j;
                const int tok = c >> 3, koff = (c & 7) * 4;
                pa[j] = *(const float4*)(x + (size_t)(tokRow + tok) * DDIM + kb + koff);
            }
            #pragma unroll
            for (int j = 0; j < 2; j++) {
                const int c = tid + 256 * j;
                const int bk = c >> 4, bne = (c & 15) * 4;
                pb[j] = *(const float4*)(W + (size_t)(kb + bk) * NEXP + bne);
            }
        }

        const uint32_t* Ah = &smw[((buf * 2 + 0) * BM) * A_STRIDE];
        const uint32_t* Al = &smw[((buf * 2 + 1) * BM) * A_STRIDE];
        const uint32_t* Bh = &smw[A_WORDS + ((buf * 2 + 0) * KC) * B_STRIDE];
        const uint32_t* Bl = &smw[A_WORDS + ((buf * 2 + 1) * KC) * B_STRIDE];

        #pragma unroll
        for (int s = 0; s < 4; ++s) {
            const int k0 = s * 8;
            uint32_t a_h[4], a_l[4], b_h[4][2], b_l[4][2];
            #pragma unroll
            for (int c = 0; c < 4; c++) {
                const int row = tokW + g + ((c & 1) << 3);
                const int col = k0 + t + ((c >> 1) << 2);
                a_h[c] = Ah[row * A_STRIDE + col];
                a_l[c] = Al[row * A_STRIDE + col];
            }
            #pragma unroll
            for (int ni = 0; ni < 4; ni++) {
                #pragma unroll
                for (int c = 0; c < 2; c++) {
                    const int row = k0 + t + (c << 2);
                    const int col = nW + ni * 8 + g;
                    b_h[ni][c] = Bh[row * B_STRIDE + col];
                    b_l[ni][c] = Bl[row * B_STRIDE + col];
                }
            }
            #pragma unroll
            for (int ni = 0; ni < 4; ni++) {
                MMA_TF32(acc_hh[ni], a_h, b_h[ni]);
                MMA_TF32(acc_sm[ni], a_h, b_l[ni]);
                MMA_TF32(acc_sm[ni], a_l, b_h[ni]);
            }
        }

        if (kt + 1 < NC) {
            const int nb = buf ^ 1;
            #pragma unroll
            for (int j = 0; j < 2; j++) {
                const int c = tid + 256 * j;
                const int tok = c >> 3, koff = (c & 7) * 4;
                float vv[4] = {pa[j].x, pa[j].y, pa[j].z, pa[j].w};
                uint32_t hi[4], lo[4];
                #pragma unroll
                for (int q = 0; q < 4; q++) {
                    hi[q] = tf32r(vv[q]);
                    lo[q] = tf32r(vv[q] - __uint_as_float(hi[q]));
                }
                const int off = tok * A_STRIDE + koff;
                *(uint4*)&smw[((nb * 2 + 0) * BM) * A_STRIDE + off] = make_uint4(hi[0], hi[1], hi[2], hi[3]);
                *(uint4*)&smw[((nb * 2 + 1) * BM) * A_STRIDE + off] = make_uint4(lo[0], lo[1], lo[2], lo[3]);
            }
            #pragma unroll
            for (int j = 0; j < 2; j++) {
                const int c = tid + 256 * j;
                const int bk = c >> 4, bne = (c & 15) * 4;
                float vv[4] = {pb[j].x, pb[j].y, pb[j].z, pb[j].w};
                uint32_t hi[4], lo[4];
                #pragma unroll
                for (int q = 0; q < 4; q++) {
                    hi[q] = tf32r(vv[q]);
                    lo[q] = tf32r(vv[q] - __uint_as_float(hi[q]));
                }
                const int off = bk * B_STRIDE + bne;
                *(uint4*)&smw[A_WORDS + ((nb * 2 + 0) * KC) * B_STRIDE + off] = make_uint4(hi[0], hi[1], hi[2], hi[3]);
                *(uint4*)&smw[A_WORDS + ((nb * 2 + 1) * KC) * B_STRIDE + off] = make_uint4(lo[0], lo[1], lo[2], lo[3]);
            }
        }
        __syncthreads();
        buf ^= 1;
    }

    // ---- epilogue: bias + sigmoid, scores ----
    #pragma unroll
    for (int ni = 0; ni < 4; ni++) {
        const int r0 = tokW + g;
        const int r1 = r0 + 8;
        const int c0 = nW + ni * 8 + 2 * t;
        const float b0 = bias[c0], b1 = bias[c0 + 1];
        float z[4] = {(acc_hh[ni][0] + acc_sm[ni][0]) + b0,
                      (acc_hh[ni][1] + acc_sm[ni][1]) + b1,
                      (acc_hh[ni][2] + acc_sm[ni][2]) + b0,
                      (acc_hh[ni][3] + acc_sm[ni][3]) + b1};
        float s[4];
        #pragma unroll
        for (int q = 0; q < 4; q++) {
            if (z[q] >= 0.0f) s[q] = 1.0f / (1.0f + expf(-z[q]));
            else { float e = expf(z[q]); s[q] = e / (1.0f + e); }
        }
        Ss[r0 * 65 + c0]     = s[0];
        Ss[r0 * 65 + c0 + 1] = s[1];
        Ss[r1 * 65 + c0]     = s[2];
        Ss[r1 * 65 + c0 + 1] = s[3];
        *(float2*)(sc_out + (size_t)(tokRow + r0) * NEXP + c0) = make_float2(s[0], s[1]);
        *(float2*)(sc_out + (size_t)(tokRow + r1) * NEXP + c0) = make_float2(s[2], s[3]);
    }

    int* flagcnt  = (int*)(smw + FLAGC_OFF);
    int* flaglist = (int*)(smw + FLAGL_OFF);
    if (tid == 0) *flagcnt = 0;
    __syncthreads();

    // ---- top-9 per token; flag knife-edge tokens ----
    if (tid < BM) {
        float vals[9];
        int   ids[9];
        #pragma unroll
        for (int j = 0; j < 9; j++) { vals[j] = -1e30f; ids[j] = 0; }
        for (int e = 0; e < NEXP; e++) {
            float sv = Ss[tid * 65 + e];
            if (sv > vals[8]) {
                int p = 8;
                while (p > 0 && sv > vals[p - 1]) {
                    vals[p] = vals[p - 1]; ids[p] = ids[p - 1]; p--;
                }
                vals[p] = sv; ids[p] = e;
            }
        }
        bool knife = false;
        #pragma unroll
        for (int j = 0; j < 8; j++)
            if (vals[j] - vals[j + 1] < 1e-5f) knife = true;

        if (!knife) {
            float sum = 0.0f;
            #pragma unroll
            for (int j = 0; j < TOPK; j++) sum += vals[j];
            const float inv = 1.0f / sum;
            const size_t base = (size_t)(tokRow + tid) * TOPK;
            #pragma unroll
            for (int j = 0; j < TOPK; j++) {
                g_out[base + j]   = vals[j] * inv;
                idx_out[base + j] = (float)ids[j];
            }
        } else {
            int pos = atomicAdd(flagcnt, 1);
            flaglist[pos] = tid;
        }
    }
    __syncthreads();

    // ---- flagged tokens: bit-exact R5-order replay (64 exp x 4 threads,
    //      each thread does 2 superchunks sequentially; strict left folds) ----
    const int nflag = *flagcnt;
    float* part   = (float*)(smw + PART_OFF);   // [64 exp][8 sc]
    float* exactf = (float*)(smw + EXACT_OFF);  // [64]
    for (int i = 0; i < nflag; i++) {
        const int tok = flaglist[i];
        {
            const int e = tid & 63;
            const int h = tid >> 6;              // 0..3
            const float* xr = x + (size_t)(tokRow + tok) * DDIM;
            const float* wp = W + e;
            #pragma unroll
            for (int hs = 0; hs < 2; hs++) {
                const int sc = 2 * h + hs;
                float sup = 0.0f;
                for (int t2 = 0; t2 < 16; t2++) {
                    const int k0 = sc * 256 + t2 * 16;
                    float tile = __fmul_rn(xr[k0], wp[(size_t)k0 * NEXP]);
                    #pragma unroll
                    for (int kk = 1; kk < 16; kk++)
                        tile = __fmaf_rn(xr[k0 + kk], wp[(size_t)(k0 + kk) * NEXP], tile);
                    sup = (t2 == 0) ? tile : __fadd_rn(sup, tile);
                }
                part[e * 8 + sc] = sup;
            }
        }
        __syncthreads();
        if (tid < NEXP) {
            float grand = part[tid * 8 + 0];
            #pragma unroll
            for (int sc = 1; sc < 8; sc++)
                grand = __fadd_rn(grand, part[tid * 8 + sc]);
            float z = grand + bias[tid];
            float s;
            if (z >= 0.0f) {
                s = 1.0f / (1.0f + expf(-z));
            } else {
                float e2 = expf(z);
                s = e2 / (1.0f + e2);
            }
            exactf[tid] = s;
        }
        __syncthreads();
        if (tid == 0) {
            float vals[TOPK];
            int   ids[TOPK];
            #pragma unroll
            for (int j = 0; j < TOPK; j++) { vals[j] = -1e30f; ids[j] = 0; }
            for (int e2 = 0; e2 < NEXP; e2++) {
                float sv = exactf[e2];
                if (sv > vals[TOPK - 1]) {
                    int p = TOPK - 1;
                    while (p > 0 && sv > vals[p - 1]) {
                        vals[p] = vals[p - 1]; ids[p] = ids[p - 1]; p--;
                    }
                    vals[p] = sv; ids[p] = e2;
                }
            }
            float sum = 0.0f;
            #pragma unroll
            for (int j = 0; j < TOPK; j++) sum += vals[j];
            const float inv = 1.0f / sum;
            const size_t base = (size_t)(tokRow + tok) * TOPK;
            #pragma unroll
            for (int j = 0; j < TOPK; j++) {
                g_out[base + j]   = vals[j] * inv;
                idx_out[base + j] = (float)ids[j];
            }
        }
        __syncthreads();
    }
}

extern "C" void kernel_launch(void* const* d_in, const int* in_sizes, int n_in,
                              void* d_out, int out_size)
{
    const float* x = (const float*)d_in[0];
    const float* W = (const float*)d_in[1];
    const float* b = (const float*)d_in[2];

    float* out     = (float*)d_out;
    float* g_out   = out;
    float* idx_out = out + (size_t)N_TOK * TOPK;
    float* sc_out  = out + (size_t)2 * N_TOK * TOPK;

    cudaFuncSetAttribute(noisyk_gate_mma,
                         cudaFuncAttributeMaxDynamicSharedMemorySize, SM_BYTES);
    noisyk_gate_mma<<<N_TOK / BM, THREADS, SM_BYTES>>>(x, W, b, g_out, idx_out, sc_out);
}